// round 7
// baseline (speedup 1.0000x reference)
#include <cuda_runtime.h>
#include <cuda_fp16.h>
#include <math.h>

#define NNODE 50000
#define EMB 35
#define DEG 32
#define NBH 36          // halves per nb row (35 ch + 1 zero pad) = 72B = 9 ull
#define MSTR 36         // g_m row stride (floats) -> 16B-aligned float4 writes

typedef unsigned long long ull;

// ---------------- scratch (device globals; no runtime allocation) ----------------
__device__ __half g_nbh[4][NNODE * NBH];   // transformed neighbor rows, fp16, 72B/row
__device__ float  g_sb[4][NNODE];          // dst-side attention score (fp32, compact)
__device__ float  g_sa[4][NNODE];          // src-side attention score
__device__ float  g_m [4][NNODE * MSTR];   // aggregation results (padded rows)

// ---------------- packed f32x2 helpers ----------------
static __device__ __forceinline__ ull pack2(float a, float b) {
    ull r;
    unsigned int lo = __float_as_uint(a), hi = __float_as_uint(b);
    asm("mov.b64 %0, {%1, %2};" : "=l"(r) : "r"(lo), "r"(hi));
    return r;
}
static __device__ __forceinline__ void unpack2(ull v, float &a, float &b) {
    unsigned int lo, hi;
    asm("mov.b64 {%0, %1}, %2;" : "=r"(lo), "=r"(hi) : "l"(v));
    a = __uint_as_float(lo);
    b = __uint_as_float(hi);
}
#define FMA2(d, a, b, c) \
    asm("fma.rn.f32x2 %0, %1, %2, %3;" : "=l"(d) : "l"(a), "l"(b), "l"(c))

// ---------------- kernel args ----------------
struct TArgs {
    const float* fa;
    const float* fb;
    const float* W[4];
    const float* b[4];
    const float* att[4];
};
struct AArgs {
    const int* dst[4];
};

// =====================================================================
// Kernel 1: stage one feature array per block (coalesced), then:
//   - GEMM for the two jobs whose fsrc == staged array (nb fp16 + s_b)
//   - s_a dots for the two jobs whose fdst == staged array
// s=0 stages fa (GEMM jobs 2,3; s_a jobs 0,1); s=1 stages fb (GEMM 0,1; s_a 2,3).
// 2 threads per row (half-channel split). 256 threads = 128 rows.
// =====================================================================
__global__ __launch_bounds__(256) void transform_kernel(TArgs args) {
    const int s   = blockIdx.y;
    const int jg0 = s ? 0 : 2;      // GEMM jobs jg0, jg0+1
    const int js0 = s ? 2 : 0;      // s_a jobs js0, js0+1
    const float* __restrict__ farr = s ? args.fb : args.fa;

    __shared__ __align__(16) float Xs[128 * 37];      // 18944B staged rows
    __shared__ __align__(16) ull wp[2][EMB * 18];     // packed W cols (pairs), 10080B
    __shared__ __align__(16) ull bp[2][18];
    __shared__ __align__(16) ull ahp[2][18];
    __shared__ __align__(16) float alo[2][36];

    const int tid = threadIdx.x;
    for (int idx = tid; idx < 2 * EMB * 18; idx += 256) {
        int jj = idx / (EMB * 18);
        int r  = idx - jj * (EMB * 18);
        int k = r / 18, i = r % 18, c = 2 * i;
        const float* W = args.W[jg0 + jj];
        wp[jj][r] = pack2(W[k * EMB + c], (c + 1 < EMB) ? W[k * EMB + c + 1] : 0.0f);
    }
    if (tid < 36) {
        int jj = tid / 18, i = tid % 18, c = 2 * i;
        const float* bv  = args.b[jg0 + jj];
        const float* att = args.att[jg0 + jj];
        bp[jj][i]  = pack2(bv[c],        (c + 1 < EMB) ? bv[c + 1]        : 0.0f);
        ahp[jj][i] = pack2(att[EMB + c], (c + 1 < EMB) ? att[EMB + c + 1] : 0.0f);
    }
    if (tid < 72) {
        int jj = tid / 36, t = tid % 36;
        alo[jj][t] = (t < EMB) ? args.att[js0 + jj][t] : 0.0f;
    }

    const int base  = blockIdx.x * 128;
    const int nrows = min(128, NNODE - base);
    const int total = nrows * EMB;
    {
        const float* __restrict__ src = farr + base * EMB;
        for (int g = tid; g < total; g += 256)
            Xs[(g / EMB) * 37 + (g % EMB)] = src[g];
    }
    __syncthreads();

    int row_l = tid >> 1;
    const int half = tid & 1;
    const bool valid = (row_l < nrows);
    if (!valid) row_l = nrows - 1;          // keep warp converged for shfl
    const int row = base + row_l;
    const float* xrs = Xs + row_l * 37;

    // ---- GEMM half-rows for both jobs ----
    ull a0[9], a1[9];
#pragma unroll
    for (int i = 0; i < 9; i++) { a0[i] = bp[0][9 * half + i]; a1[i] = bp[1][9 * half + i]; }

#pragma unroll 5
    for (int k = 0; k < EMB; k++) {
        float xv = xrs[k];
        ull xx = pack2(xv, xv);
        const ull* w0 = wp[0] + k * 18 + 9 * half;
        const ull* w1 = wp[1] + k * 18 + 9 * half;
#pragma unroll
        for (int i = 0; i < 9; i++) {
            FMA2(a0[i], w0[i], xx, a0[i]);
            FMA2(a1[i], w1[i], xx, a1[i]);
        }
    }

    // ---- s_b for both GEMM jobs (pair-combine via shfl) ----
    {
        ull sp0 = 0ull, sp1 = 0ull;
#pragma unroll
        for (int i = 0; i < 9; i++) {
            FMA2(sp0, a0[i], ahp[0][9 * half + i], sp0);
            FMA2(sp1, a1[i], ahp[1][9 * half + i], sp1);
        }
        float x0, y0, x1, y1;
        unpack2(sp0, x0, y0);
        unpack2(sp1, x1, y1);
        float p0 = x0 + y0, p1 = x1 + y1;
        p0 += __shfl_xor_sync(0xffffffffu, p0, 1);
        p1 += __shfl_xor_sync(0xffffffffu, p1, 1);
        if (valid && half == 0) {
            g_sb[jg0][row]     = p0;
            g_sb[jg0 + 1][row] = p1;
        }
    }

    // ---- fp16 stores (9 uints per half per job) ----
    if (valid) {
        unsigned int* r0 =
            reinterpret_cast<unsigned int*>(&g_nbh[jg0][row * NBH]) + 9 * half;
        unsigned int* r1 =
            reinterpret_cast<unsigned int*>(&g_nbh[jg0 + 1][row * NBH]) + 9 * half;
#pragma unroll
        for (int i = 0; i < 9; i++) {
            float f0, f1;
            unpack2(a0[i], f0, f1);
            __half2 h = __floats2half2_rn(f0, f1);
            r0[i] = *reinterpret_cast<unsigned int*>(&h);
            unpack2(a1[i], f0, f1);
            h = __floats2half2_rn(f0, f1);
            r1[i] = *reinterpret_cast<unsigned int*>(&h);
        }
    }

    // ---- s_a for the two fdst jobs (k-split between halves, shfl combine) ----
    {
        float sa0 = 0.0f, sa1 = 0.0f;
        const int k0 = half ? 18 : 0;
        const int k1 = half ? EMB : 18;
        for (int k = k0; k < k1; k++) {
            float xv = xrs[k];
            sa0 = fmaf(xv, alo[0][k], sa0);
            sa1 = fmaf(xv, alo[1][k], sa1);
        }
        sa0 += __shfl_xor_sync(0xffffffffu, sa0, 1);
        sa1 += __shfl_xor_sync(0xffffffffu, sa1, 1);
        if (valid && half == 0) {
            g_sa[js0][row]     = sa0;
            g_sa[js0 + 1][row] = sa1;
        }
    }
}

// =====================================================================
// Kernel 2: attention aggregation. One warp per node.
// Row = 9 x 8B. lane = sub*9 + piece: 3 edges gathered per warp LDG.64.
// =====================================================================
__global__ __launch_bounds__(256) void agg_kernel(AArgs args) {
    const int jid = blockIdx.y;
    const ull* __restrict__ nb = reinterpret_cast<const ull*>(g_nbh[jid]);
    const float* __restrict__ sbv = g_sb[jid];
    const float* __restrict__ sav = g_sa[jid];
    const int*   __restrict__ dst = args.dst[jid];
    float* __restrict__ m = g_m[jid];

    __shared__ float sw[8][36];
    __shared__ int   soff[8][36];

    const int wid  = threadIdx.x >> 5;
    const int lane = threadIdx.x & 31;
    const int node = blockIdx.x * 8 + wid;
    if (node >= NNODE) return;

    const int d = dst[node * DEG + lane];
    float x = sav[node] + sbv[d];
    float e = (x > 0.0f) ? x : 0.1f * expm1f(x);   // elu(alpha=0.1)
    float w = expf(e);

    float wsum = w;
#pragma unroll
    for (int o = 16; o; o >>= 1) wsum += __shfl_xor_sync(0xffffffffu, wsum, o);

    sw[wid][lane]   = w;
    soff[wid][lane] = d * 9;
    if (lane == 0) { sw[wid][32] = 0.0f; soff[wid][32] = 0; }
    __syncwarp();

    const int sub   = (lane < 27) ? (lane / 9) : 2;
    const int piece = (lane < 27) ? (lane % 9) : (lane - 27);

    float a0 = 0.0f, a1 = 0.0f, a2 = 0.0f, a3 = 0.0f;
#pragma unroll
    for (int it = 0; it < 11; it++) {
        int j = it * 3 + sub;
        float wj = sw[wid][j];
        ull v = nb[soff[wid][j] + piece];
        unsigned int lo, hi;
        asm("mov.b64 {%0, %1}, %2;" : "=r"(lo), "=r"(hi) : "l"(v));
        float2 f0 = __half22float2(*reinterpret_cast<__half2*>(&lo));
        float2 f1 = __half22float2(*reinterpret_cast<__half2*>(&hi));
        a0 = fmaf(wj, f0.x, a0);
        a1 = fmaf(wj, f0.y, a1);
        a2 = fmaf(wj, f1.x, a2);
        a3 = fmaf(wj, f1.y, a3);
    }

    {
        float t, u;
        t = __shfl_down_sync(0xffffffffu, a0, 9);
        u = __shfl_down_sync(0xffffffffu, a0, 18);
        a0 += t + u;
        t = __shfl_down_sync(0xffffffffu, a1, 9);
        u = __shfl_down_sync(0xffffffffu, a1, 18);
        a1 += t + u;
        t = __shfl_down_sync(0xffffffffu, a2, 9);
        u = __shfl_down_sync(0xffffffffu, a2, 18);
        a2 += t + u;
        t = __shfl_down_sync(0xffffffffu, a3, 9);
        u = __shfl_down_sync(0xffffffffu, a3, 18);
        a3 += t + u;
    }

    if (lane < 9) {
        float inv = 1.0f / wsum;
        float4 o = make_float4(a0 * inv, a1 * inv, a2 * inv, a3 * inv);
        *reinterpret_cast<float4*>(m + node * MSTR + 4 * lane) = o;
    }
}

// =====================================================================
// Kernel 3 (merged a+b): out = prelu([feat, m_pos, m_neg] @ W1 + b1) @ W2 + b2
// 4 threads per node. Node inputs staged coalesced into smem (stride 108);
// the same buffer is reused for the h exchange after a barrier.
// =====================================================================
__global__ __launch_bounds__(256, 3) void update_kernel(
    const float* __restrict__ fa, const float* __restrict__ fb,
    const float* __restrict__ W1, const float* __restrict__ b1,
    const float* __restrict__ alpha_p,
    const float* __restrict__ W2, const float* __restrict__ b2,
    float* __restrict__ out)
{
    __shared__ __align__(16) float W1sh[105 * 72];   // 30240B
    __shared__ __align__(16) ull   w2p[70 * 18];     // 10080B
    __shared__ __align__(16) float Xs[64 * 108];     // 27648B; reused as h[64*73]
    __shared__ __align__(16) ull b1p[36];
    __shared__ __align__(16) ull b2p[18];

    const int tid = threadIdx.x;
    for (int i = tid; i < 105 * 72; i += 256) {
        int k = i / 72, c = i % 72;
        W1sh[i] = (c < 70) ? W1[k * 70 + c] : 0.0f;
    }
    for (int i = tid; i < 70 * 18; i += 256) {
        int k = i / 18, j = i % 18;
        int c = 2 * j;
        w2p[i] = pack2(W2[k * EMB + c], (c + 1 < EMB) ? W2[k * EMB + c + 1] : 0.0f);
    }
    if (tid < 36) {
        int c = 2 * tid;
        b1p[tid] = pack2(b1[c], (c + 1 < 70) ? b1[c + 1] : 0.0f);
    }
    if (tid < 18) {
        int c = 2 * tid;
        b2p[tid] = pack2(b2[c], (c + 1 < EMB) ? b2[c + 1] : 0.0f);
    }

    const int base = blockIdx.x * 64;

    // ---- stage x rows: feat -> [0,35), m0 -> [36,72), m1 -> [72,108) ----
    for (int g = tid; g < 64 * EMB; g += 256) {
        int nl = g / EMB, c = g - nl * EMB;
        int n = base + nl;
        if (n < 2 * NNODE) {
            Xs[nl * 108 + c] = (n < NNODE) ? fa[n * EMB + c]
                                           : fb[(n - NNODE) * EMB + c];
        }
    }
    for (int g = tid; g < 64 * 36; g += 256) {
        int nl = g / 36, c = g - nl * 36;
        int n = base + nl;
        if (n < 2 * NNODE) {
            if (n < NNODE) {
                Xs[nl * 108 + 36 + c] = g_m[0][n * MSTR + c];
                Xs[nl * 108 + 72 + c] = g_m[1][n * MSTR + c];
            } else {
                int nn = n - NNODE;
                Xs[nl * 108 + 36 + c] = g_m[2][nn * MSTR + c];
                Xs[nl * 108 + 72 + c] = g_m[3][nn * MSTR + c];
            }
        }
    }
    __syncthreads();

    const int node_l = tid >> 2;
    const int role   = tid & 3;
    const int node   = base + node_l;
    const bool valid = (node < 2 * NNODE);
    const float alpha = __ldg(alpha_p);

    // ---- GEMM1: this role computes h pairs [9*role, 9*role+9) ----
    ull acc[9];
#pragma unroll
    for (int i = 0; i < 9; i++) acc[i] = b1p[9 * role + i];

    const float* xb = Xs + node_l * 108;
    const ull* w1base = reinterpret_cast<const ull*>(W1sh) + 9 * role;
    const int poff[3] = { 0, 36, 72 };
#pragma unroll
    for (int part = 0; part < 3; part++) {
        const float* x = xb + poff[part];
        const ull* wb = w1base + (part * EMB) * 36;
#pragma unroll 5
        for (int k = 0; k < EMB; k++) {
            float xv = x[k];
            ull xx = pack2(xv, xv);
            const ull* wr = wb + k * 36;
#pragma unroll
            for (int i = 0; i < 9; i++) FMA2(acc[i], wr[i], xx, acc[i]);
        }
    }
    __syncthreads();   // all Xs reads done; buffer now reused for h

    // ---- PReLU, publish h (quad lives in one warp) ----
    float* hrow = Xs + node_l * 73;
#pragma unroll
    for (int i = 0; i < 9; i++) {
        float h0, h1;
        unpack2(acc[i], h0, h1);
        h0 = (h0 > 0.0f) ? h0 : alpha * h0;
        h1 = (h1 > 0.0f) ? h1 : alpha * h1;
        int c = 18 * role + 2 * i;
        hrow[c]     = h0;
        hrow[c + 1] = h1;
    }
    __syncwarp();

    // ---- GEMM2: role owns output pairs [p0, p0+np) ----
    const int p0 = (role < 2) ? role * 5 : 10 + (role - 2) * 4;
    const int np = (role < 2) ? 5 : 4;

    ull acc2[5];
#pragma unroll
    for (int q = 0; q < 5; q++) acc2[q] = (q < np) ? b2p[p0 + q] : 0ull;

#pragma unroll 2
    for (int k = 0; k < 70; k++) {
        float hv = hrow[k];
        ull xx = pack2(hv, hv);
        const ull* wr = w2p + k * 18 + p0;
#pragma unroll
        for (int q = 0; q < 5; q++)
            if (q < np) FMA2(acc2[q], wr[q], xx, acc2[q]);
    }

    if (valid) {
        float* orow = out + node * EMB;
#pragma unroll
        for (int q = 0; q < 5; q++) {
            if (q < np) {
                float v0, v1;
                unpack2(acc2[q], v0, v1);
                int c = 2 * (p0 + q);
                orow[c] = v0;
                if (c + 1 < EMB) orow[c + 1] = v1;
            }
        }
    }
}

// =====================================================================
// launch
// =====================================================================
extern "C" void kernel_launch(void* const* d_in, const int* in_sizes, int n_in,
                              void* d_out, int out_size) {
    const float* fa = (const float*)d_in[0];
    const float* fb = (const float*)d_in[1];

    TArgs t;
    t.fa = fa;
    t.fb = fb;
    for (int j = 0; j < 4; j++) {
        t.W[j]   = (const float*)d_in[6 + 3 * j];
        t.b[j]   = (const float*)d_in[7 + 3 * j];
        t.att[j] = (const float*)d_in[8 + 3 * j];
    }
    AArgs a;
    a.dst[0] = (const int*)d_in[2];
    a.dst[1] = (const int*)d_in[3];
    a.dst[2] = (const int*)d_in[4];
    a.dst[3] = (const int*)d_in[5];

    const float* W1 = (const float*)d_in[18];
    const float* b1 = (const float*)d_in[19];
    const float* al = (const float*)d_in[20];
    const float* W2 = (const float*)d_in[21];
    const float* b2 = (const float*)d_in[22];
    float* out = (float*)d_out;

    dim3 tg((NNODE + 127) / 128, 2);
    transform_kernel<<<tg, 256>>>(t);

    dim3 ag((NNODE + 7) / 8, 4);
    agg_kernel<<<ag, 256>>>(a);

    dim3 ug((2 * NNODE + 63) / 64);
    update_kernel<<<ug, 256>>>(fa, fb, W1, b1, al, W2, b2, out);
}

// round 8
// speedup vs baseline: 1.0741x; 1.0741x over previous
#include <cuda_runtime.h>
#include <cuda_fp16.h>
#include <math.h>

#define NNODE 50000
#define EMB 35
#define DEG 32
#define NBH 36          // halves per nb row (35 ch + 1 zero pad) = 72B = 9 ull
#define MSTR 36         // g_m row stride (floats) -> 16B-aligned float4 writes

typedef unsigned long long ull;

// ---------------- scratch (device globals; no runtime allocation) ----------------
__device__ __half g_nbh[4][NNODE * NBH];   // transformed neighbor rows, fp16, 72B/row
__device__ float  g_sb[4][NNODE];          // dst-side attention score (fp32, compact)
__device__ float  g_sa[4][NNODE];          // src-side attention score
__device__ float  g_m [4][NNODE * MSTR];   // aggregation results (padded rows)

// ---------------- packed f32x2 helpers ----------------
static __device__ __forceinline__ ull pack2(float a, float b) {
    ull r;
    unsigned int lo = __float_as_uint(a), hi = __float_as_uint(b);
    asm("mov.b64 %0, {%1, %2};" : "=l"(r) : "r"(lo), "r"(hi));
    return r;
}
static __device__ __forceinline__ void unpack2(ull v, float &a, float &b) {
    unsigned int lo, hi;
    asm("mov.b64 {%0, %1}, %2;" : "=r"(lo), "=r"(hi) : "l"(v));
    a = __uint_as_float(lo);
    b = __uint_as_float(hi);
}
#define FMA2(d, a, b, c) \
    asm("fma.rn.f32x2 %0, %1, %2, %3;" : "=l"(d) : "l"(a), "l"(b), "l"(c))

// ---------------- kernel args ----------------
struct TArgs {
    const float* fsrc[4];
    const float* fdst[4];
    const float* W[4];
    const float* b[4];
    const float* att[4];
};
struct AArgs {
    const int* dst[4];
};

// =====================================================================
// Kernel 1 (R6 form): nb = fsrc @ W + b (fp16); s_b = nb.att_hi; s_a = fdst.att_lo
// 2 threads per row (half-channel split). jobs on gridDim.y.
// =====================================================================
__global__ __launch_bounds__(256) void transform_kernel(TArgs args) {
    const int jid = blockIdx.y;
    const float* __restrict__ W   = args.W[jid];
    const float* __restrict__ bv  = args.b[jid];
    const float* __restrict__ att = args.att[jid];

    __shared__ __align__(16) float Wsh[EMB * 36];   // 5040B
    __shared__ __align__(16) ull bp[18];
    __shared__ __align__(16) ull ahp[18];
    __shared__ __align__(16) float alo[36];

    const int tid = threadIdx.x;
    for (int i = tid; i < EMB * 36; i += 256) {
        int k = i / 36, c = i % 36;
        Wsh[i] = (c < EMB) ? W[k * EMB + c] : 0.0f;
    }
    if (tid < 18) {
        int c = 2 * tid;
        bp[tid]  = pack2(bv[c],        (c + 1 < EMB) ? bv[c + 1]        : 0.0f);
        ahp[tid] = pack2(att[EMB + c], (c + 1 < EMB) ? att[EMB + c + 1] : 0.0f);
    }
    if (tid < 36) alo[tid] = (tid < EMB) ? att[tid] : 0.0f;
    __syncthreads();

    const int row_l = tid >> 1;
    const int half  = tid & 1;
    int row = blockIdx.x * 128 + row_l;
    const bool valid = (row < NNODE);
    if (!valid) row = NNODE - 1;          // keep warp converged for shfl

    ull acc[9];
#pragma unroll
    for (int i = 0; i < 9; i++) acc[i] = bp[9 * half + i];

    const float* xr = args.fsrc[jid] + row * EMB;
#pragma unroll 5
    for (int k = 0; k < EMB; k++) {
        float xv = __ldg(xr + k);
        ull xx = pack2(xv, xv);
        const ull* wr = reinterpret_cast<const ull*>(Wsh) + k * 18 + 9 * half;
#pragma unroll
        for (int i = 0; i < 9; i++) FMA2(acc[i], wr[i], xx, acc[i]);
    }

    {
        ull sp = 0ull;
#pragma unroll
        for (int i = 0; i < 9; i++) FMA2(sp, acc[i], ahp[9 * half + i], sp);
        float x0, y0;
        unpack2(sp, x0, y0);
        float ps = x0 + y0;
        ps += __shfl_xor_sync(0xffffffffu, ps, 1);
        if (valid && half == 0) g_sb[jid][row] = ps;
    }

    if (valid) {
        unsigned int* r =
            reinterpret_cast<unsigned int*>(&g_nbh[jid][row * NBH]) + 9 * half;
#pragma unroll
        for (int i = 0; i < 9; i++) {
            float f0, f1;
            unpack2(acc[i], f0, f1);
            __half2 h = __floats2half2_rn(f0, f1);
            r[i] = *reinterpret_cast<unsigned int*>(&h);
        }
    }

    {
        const float* yr = args.fdst[jid] + row * EMB;
        float sa = 0.0f;
        int k0 = half ? 18 : 0;
        int k1 = half ? EMB : 18;
        for (int k = k0; k < k1; k++) sa = fmaf(__ldg(yr + k), alo[k], sa);
        sa += __shfl_xor_sync(0xffffffffu, sa, 1);
        if (valid && half == 0) g_sa[jid][row] = sa;
    }
}

// =====================================================================
// Kernel 2 (R6 form): attention aggregation. One warp per node.
// Row = 9 x 8B. lane = sub*9 + piece: 3 edges gathered per warp LDG.64.
// =====================================================================
__global__ __launch_bounds__(256) void agg_kernel(AArgs args) {
    const int jid = blockIdx.y;
    const ull* __restrict__ nb = reinterpret_cast<const ull*>(g_nbh[jid]);
    const float* __restrict__ sbv = g_sb[jid];
    const float* __restrict__ sav = g_sa[jid];
    const int*   __restrict__ dst = args.dst[jid];
    float* __restrict__ m = g_m[jid];

    __shared__ float sw[8][36];
    __shared__ int   soff[8][36];

    const int wid  = threadIdx.x >> 5;
    const int lane = threadIdx.x & 31;
    const int node = blockIdx.x * 8 + wid;
    if (node >= NNODE) return;

    const int d = dst[node * DEG + lane];
    float x = sav[node] + sbv[d];
    float e = (x > 0.0f) ? x : 0.1f * expm1f(x);   // elu(alpha=0.1)
    float w = expf(e);

    float wsum = w;
#pragma unroll
    for (int o = 16; o; o >>= 1) wsum += __shfl_xor_sync(0xffffffffu, wsum, o);

    sw[wid][lane]   = w;
    soff[wid][lane] = d * 9;
    if (lane == 0) { sw[wid][32] = 0.0f; soff[wid][32] = 0; }
    __syncwarp();

    const int sub   = (lane < 27) ? (lane / 9) : 2;
    const int piece = (lane < 27) ? (lane % 9) : (lane - 27);

    float a0 = 0.0f, a1 = 0.0f, a2 = 0.0f, a3 = 0.0f;
#pragma unroll
    for (int it = 0; it < 11; it++) {
        int j = it * 3 + sub;
        float wj = sw[wid][j];
        ull v = nb[soff[wid][j] + piece];
        unsigned int lo, hi;
        asm("mov.b64 {%0, %1}, %2;" : "=r"(lo), "=r"(hi) : "l"(v));
        float2 f0 = __half22float2(*reinterpret_cast<__half2*>(&lo));
        float2 f1 = __half22float2(*reinterpret_cast<__half2*>(&hi));
        a0 = fmaf(wj, f0.x, a0);
        a1 = fmaf(wj, f0.y, a1);
        a2 = fmaf(wj, f1.x, a2);
        a3 = fmaf(wj, f1.y, a3);
    }

    {
        float t, u;
        t = __shfl_down_sync(0xffffffffu, a0, 9);
        u = __shfl_down_sync(0xffffffffu, a0, 18);
        a0 += t + u;
        t = __shfl_down_sync(0xffffffffu, a1, 9);
        u = __shfl_down_sync(0xffffffffu, a1, 18);
        a1 += t + u;
        t = __shfl_down_sync(0xffffffffu, a2, 9);
        u = __shfl_down_sync(0xffffffffu, a2, 18);
        a2 += t + u;
        t = __shfl_down_sync(0xffffffffu, a3, 9);
        u = __shfl_down_sync(0xffffffffu, a3, 18);
        a3 += t + u;
    }

    if (lane < 9) {
        float inv = 1.0f / wsum;
        float4 o = make_float4(a0 * inv, a1 * inv, a2 * inv, a3 * inv);
        *reinterpret_cast<float4*>(m + node * MSTR + 4 * lane) = o;
    }
}

// =====================================================================
// Kernel 3: out = prelu([feat, m_pos, m_neg] @ W1 + b1) @ W2 + b2
// 4 threads per node. Quad-cooperative x loads: each role loads 27 of the
// 105 x values (consecutive within quad -> shared sectors), k-loop gets
// x_k via width-4 shuffles. h exchanged via smem (quad in one warp).
// =====================================================================
__global__ __launch_bounds__(256, 3) void update_kernel(
    const float* __restrict__ fa, const float* __restrict__ fb,
    const float* __restrict__ W1, const float* __restrict__ b1,
    const float* __restrict__ alpha_p,
    const float* __restrict__ W2, const float* __restrict__ b2,
    float* __restrict__ out)
{
    __shared__ __align__(16) float W1sh[105 * 72];   // 30240B
    __shared__ __align__(16) ull   w2p[70 * 18];     // 10080B
    __shared__ __align__(16) float hs[64 * 73];      // 18688B
    __shared__ __align__(16) ull b1p[36];
    __shared__ __align__(16) ull b2p[18];

    const int tid = threadIdx.x;
    for (int i = tid; i < 105 * 72; i += 256) {
        int k = i / 72, c = i % 72;
        W1sh[i] = (c < 70) ? W1[k * 70 + c] : 0.0f;
    }
    for (int i = tid; i < 70 * 18; i += 256) {
        int k = i / 18, j = i % 18;
        int c = 2 * j;
        w2p[i] = pack2(W2[k * EMB + c], (c + 1 < EMB) ? W2[k * EMB + c + 1] : 0.0f);
    }
    if (tid < 36) {
        int c = 2 * tid;
        b1p[tid] = pack2(b1[c], (c + 1 < 70) ? b1[c + 1] : 0.0f);
    }
    if (tid < 18) {
        int c = 2 * tid;
        b2p[tid] = pack2(b2[c], (c + 1 < EMB) ? b2[c + 1] : 0.0f);
    }
    __syncthreads();

    const int node_l = tid >> 2;
    const int role   = tid & 3;
    const int node   = blockIdx.x * 64 + node_l;           // 0 .. 2*NNODE-1
    const bool valid = (node < 2 * NNODE);
    const int  nc    = valid ? node : (2 * NNODE - 1);

    const float* xr;
    const float* m0;
    const float* m1;
    if (nc < NNODE) {
        xr = fa + nc * EMB;
        m0 = g_m[0] + nc * MSTR;
        m1 = g_m[1] + nc * MSTR;
    } else {
        int nl = nc - NNODE;
        xr = fb + nl * EMB;
        m0 = g_m[2] + nl * MSTR;
        m1 = g_m[3] + nl * MSTR;
    }
    const float alpha = __ldg(alpha_p);

    // ---- quad-cooperative x load: this role owns x[g], g = 4*i + role ----
    float xv_[27];
#pragma unroll
    for (int i = 0; i < 27; i++) {
        int g = 4 * i + role;
        float v;
        if (g < EMB)            v = xr[g];
        else if (g < 2 * EMB)   v = m0[g - EMB];
        else if (g < 3 * EMB)   v = m1[g - 2 * EMB];
        else                    v = 0.0f;
        xv_[i] = v;
    }

    // ---- GEMM1: this role computes h pairs [9*role, 9*role+9) ----
    ull acc[9];
#pragma unroll
    for (int i = 0; i < 9; i++) acc[i] = b1p[9 * role + i];

    const ull* w1base = reinterpret_cast<const ull*>(W1sh) + 9 * role;
#pragma unroll
    for (int k = 0; k < 105; k++) {
        // owner of x_k within the quad is role k&3, slot k>>2
        float xv = __shfl_sync(0xffffffffu, xv_[k >> 2], k & 3, 4);
        ull xx = pack2(xv, xv);
        const ull* wr = w1base + k * 36;
#pragma unroll
        for (int i = 0; i < 9; i++) FMA2(acc[i], wr[i], xx, acc[i]);
    }

    // ---- PReLU, publish h to smem (quad lives in one warp) ----
    float* hrow = hs + node_l * 73;
#pragma unroll
    for (int i = 0; i < 9; i++) {
        float h0, h1;
        unpack2(acc[i], h0, h1);
        h0 = (h0 > 0.0f) ? h0 : alpha * h0;
        h1 = (h1 > 0.0f) ? h1 : alpha * h1;
        int c = 18 * role + 2 * i;
        hrow[c]     = h0;
        hrow[c + 1] = h1;
    }
    __syncwarp();

    // ---- GEMM2: role owns output pairs [p0, p0+np) ----
    const int p0 = (role < 2) ? role * 5 : 10 + (role - 2) * 4;
    const int np = (role < 2) ? 5 : 4;

    ull acc2[5];
#pragma unroll
    for (int q = 0; q < 5; q++) acc2[q] = (q < np) ? b2p[p0 + q] : 0ull;

#pragma unroll 2
    for (int k = 0; k < 70; k++) {
        float hv = hrow[k];
        ull xx = pack2(hv, hv);
        const ull* wr = w2p + k * 18 + p0;
#pragma unroll
        for (int q = 0; q < 5; q++)
            if (q < np) FMA2(acc2[q], wr[q], xx, acc2[q]);
    }

    if (valid) {
        float* orow = out + node * EMB;
#pragma unroll
        for (int q = 0; q < 5; q++) {
            if (q < np) {
                float v0, v1;
                unpack2(acc2[q], v0, v1);
                int c = 2 * (p0 + q);
                orow[c] = v0;
                if (c + 1 < EMB) orow[c + 1] = v1;
            }
        }
    }
}

// =====================================================================
// launch
// =====================================================================
extern "C" void kernel_launch(void* const* d_in, const int* in_sizes, int n_in,
                              void* d_out, int out_size) {
    const float* fa = (const float*)d_in[0];
    const float* fb = (const float*)d_in[1];

    TArgs t;
    const float* fsrc[4] = { fb, fb, fa, fa };
    const float* fdst[4] = { fa, fa, fb, fb };
    for (int j = 0; j < 4; j++) {
        t.fsrc[j] = fsrc[j];
        t.fdst[j] = fdst[j];
        t.W[j]   = (const float*)d_in[6 + 3 * j];
        t.b[j]   = (const float*)d_in[7 + 3 * j];
        t.att[j] = (const float*)d_in[8 + 3 * j];
    }
    AArgs a;
    a.dst[0] = (const int*)d_in[2];
    a.dst[1] = (const int*)d_in[3];
    a.dst[2] = (const int*)d_in[4];
    a.dst[3] = (const int*)d_in[5];

    const float* W1 = (const float*)d_in[18];
    const float* b1 = (const float*)d_in[19];
    const float* al = (const float*)d_in[20];
    const float* W2 = (const float*)d_in[21];
    const float* b2 = (const float*)d_in[22];
    float* out = (float*)d_out;

    dim3 tg((NNODE + 127) / 128, 4);
    transform_kernel<<<tg, 256>>>(t);

    dim3 ag((NNODE + 7) / 8, 4);
    agg_kernel<<<ag, 256>>>(a);

    dim3 ug((2 * NNODE + 63) / 64);
    update_kernel<<<ug, 256>>>(fa, fb, W1, b1, al, W2, b2, out);
}

// round 9
// speedup vs baseline: 1.0781x; 1.0037x over previous
#include <cuda_runtime.h>
#include <cuda_fp16.h>
#include <math.h>

#define NNODE 50000
#define EMB 35
#define DEG 32
#define NBH 36          // halves per nb row: 35 ch + s_b(fp16) at slot 35 = 72B = 9 ull
#define MSTR 36         // g_m row stride (floats) -> 16B-aligned float4 writes

typedef unsigned long long ull;

// ---------------- scratch (device globals; no runtime allocation) ----------------
__device__ __half g_nbh[4][NNODE * NBH];   // fp16 rows; slot 35 carries s_b
__device__ float  g_sa[4][NNODE];          // src-side attention score
__device__ float  g_m [4][NNODE * MSTR];   // aggregation results (padded rows)

// ---------------- packed f32x2 helpers ----------------
static __device__ __forceinline__ ull pack2(float a, float b) {
    ull r;
    unsigned int lo = __float_as_uint(a), hi = __float_as_uint(b);
    asm("mov.b64 %0, {%1, %2};" : "=l"(r) : "r"(lo), "r"(hi));
    return r;
}
static __device__ __forceinline__ void unpack2(ull v, float &a, float &b) {
    unsigned int lo, hi;
    asm("mov.b64 {%0, %1}, %2;" : "=r"(lo), "=r"(hi) : "l"(v));
    a = __uint_as_float(lo);
    b = __uint_as_float(hi);
}
#define FMA2(d, a, b, c) \
    asm("fma.rn.f32x2 %0, %1, %2, %3;" : "=l"(d) : "l"(a), "l"(b), "l"(c))

// ---------------- kernel args ----------------
struct TArgs {
    const float* fsrc[4];
    const float* fdst[4];
    const float* W[4];
    const float* b[4];
    const float* att[4];
};
struct AArgs {
    const int* dst[4];
};

// =====================================================================
// Kernel 1: nb = fsrc @ W + b (fp16, s_b folded into slot 35);
//           s_a = fdst . att_lo.
// Two-phase smem staging (coalesced LDG, conflict-free stride-37 LDS).
// 2 threads per row (half-channel split). jobs on gridDim.y.
// =====================================================================
__global__ __launch_bounds__(256) void transform_kernel(TArgs args) {
    const int jid = blockIdx.y;
    const float* __restrict__ bv  = args.b[jid];
    const float* __restrict__ att = args.att[jid];

    __shared__ __align__(16) float Xs[128 * 37];    // 18944B staged feature rows
    __shared__ __align__(16) ull wp[EMB * 18];      // 5040B packed W col-pairs
    __shared__ __align__(16) ull bp[18];
    __shared__ __align__(16) ull ahp[18];
    __shared__ __align__(16) float alo[36];

    const int tid = threadIdx.x;
    {
        const float* __restrict__ W = args.W[jid];
        for (int r = tid; r < EMB * 18; r += 256) {
            int k = r / 18, i = r % 18, c = 2 * i;
            wp[r] = pack2(W[k * EMB + c], (c + 1 < EMB) ? W[k * EMB + c + 1] : 0.0f);
        }
    }
    if (tid < 18) {
        int c = 2 * tid;
        bp[tid]  = pack2(bv[c],        (c + 1 < EMB) ? bv[c + 1]        : 0.0f);
        ahp[tid] = pack2(att[EMB + c], (c + 1 < EMB) ? att[EMB + c + 1] : 0.0f);
    }
    if (tid < 36) alo[tid] = (tid < EMB) ? att[tid] : 0.0f;

    const int base  = blockIdx.x * 128;
    const int nrows = min(128, NNODE - base);
    const int total = nrows * EMB;

    const int row_l = tid >> 1;
    const int half  = tid & 1;
    const bool valid = (row_l < nrows);
    const int rl = valid ? row_l : 0;          // safe index; warp stays converged
    const int row = base + rl;
    const float* xrs = Xs + rl * 37;

    // ---- phase A: stage fdst, compute s_a ----
    {
        const float* __restrict__ src = args.fdst[jid] + base * EMB;
        for (int g = tid; g < total; g += 256)
            Xs[(g / EMB) * 37 + (g % EMB)] = src[g];
    }
    __syncthreads();
    {
        float sa = 0.0f;
        const int k0 = half ? 18 : 0;
        const int k1 = half ? EMB : 18;
        for (int k = k0; k < k1; k++) sa = fmaf(xrs[k], alo[k], sa);
        sa += __shfl_xor_sync(0xffffffffu, sa, 1);
        if (valid && half == 0) g_sa[jid][row] = sa;
    }
    __syncthreads();

    // ---- phase B: stage fsrc, GEMM + s_b ----
    {
        const float* __restrict__ src = args.fsrc[jid] + base * EMB;
        for (int g = tid; g < total; g += 256)
            Xs[(g / EMB) * 37 + (g % EMB)] = src[g];
    }
    __syncthreads();

    ull acc[9];
#pragma unroll
    for (int i = 0; i < 9; i++) acc[i] = bp[9 * half + i];

#pragma unroll 5
    for (int k = 0; k < EMB; k++) {
        float xv = xrs[k];
        ull xx = pack2(xv, xv);
        const ull* wr = wp + k * 18 + 9 * half;
#pragma unroll
        for (int i = 0; i < 9; i++) FMA2(acc[i], wr[i], xx, acc[i]);
    }

    // s_b = nb . att_hi; combine halves so BOTH have the full value
    float ps;
    {
        ull sp = 0ull;
#pragma unroll
        for (int i = 0; i < 9; i++) FMA2(sp, acc[i], ahp[9 * half + i], sp);
        float x0, y0;
        unpack2(sp, x0, y0);
        ps = x0 + y0;
        ps += __shfl_xor_sync(0xffffffffu, ps, 1);
    }

    // fp16 store; half1's last pair carries (ch34, s_b)
    if (valid) {
        unsigned int* r =
            reinterpret_cast<unsigned int*>(&g_nbh[jid][row * NBH]) + 9 * half;
#pragma unroll
        for (int i = 0; i < 9; i++) {
            float f0, f1;
            unpack2(acc[i], f0, f1);
            if (half == 1 && i == 8) f1 = ps;    // slot 35 := s_b
            __half2 h = __floats2half2_rn(f0, f1);
            r[i] = *reinterpret_cast<unsigned int*>(&h);
        }
    }
}

// =====================================================================
// Kernel 2: attention aggregation. One warp per node.
// s_b read from row slot 35 (3rd sector of the row phase 2 fetches anyway).
// Row = 9 x 8B. lane = sub*9 + piece: 3 edges per warp LDG.64 iteration.
// Lane piece==8 accumulates s_b garbage into g_m slot 35 (never read).
// =====================================================================
__global__ __launch_bounds__(256) void agg_kernel(AArgs args) {
    const int jid = blockIdx.y;
    const __half* __restrict__ nbh = g_nbh[jid];
    const ull* __restrict__ nb = reinterpret_cast<const ull*>(nbh);
    const float* __restrict__ sav = g_sa[jid];
    const int*   __restrict__ dst = args.dst[jid];
    float* __restrict__ m = g_m[jid];

    __shared__ float sw[8][36];
    __shared__ int   soff[8][36];

    const int wid  = threadIdx.x >> 5;
    const int lane = threadIdx.x & 31;
    const int node = blockIdx.x * 8 + wid;
    if (node >= NNODE) return;

    const int d = dst[node * DEG + lane];
    float sb = __half2float(nbh[d * NBH + 35]);
    float x = sav[node] + sb;
    float e = (x > 0.0f) ? x : 0.1f * expm1f(x);   // elu(alpha=0.1)
    float w = expf(e);

    float wsum = w;
#pragma unroll
    for (int o = 16; o; o >>= 1) wsum += __shfl_xor_sync(0xffffffffu, wsum, o);

    sw[wid][lane]   = w;
    soff[wid][lane] = d * 9;
    if (lane == 0) { sw[wid][32] = 0.0f; soff[wid][32] = 0; }
    __syncwarp();

    const int sub   = (lane < 27) ? (lane / 9) : 2;
    const int piece = (lane < 27) ? (lane % 9) : (lane - 27);

    float a0 = 0.0f, a1 = 0.0f, a2 = 0.0f, a3 = 0.0f;
#pragma unroll
    for (int it = 0; it < 11; it++) {
        int j = it * 3 + sub;
        float wj = sw[wid][j];
        ull v = nb[soff[wid][j] + piece];
        unsigned int lo, hi;
        asm("mov.b64 {%0, %1}, %2;" : "=r"(lo), "=r"(hi) : "l"(v));
        float2 f0 = __half22float2(*reinterpret_cast<__half2*>(&lo));
        float2 f1 = __half22float2(*reinterpret_cast<__half2*>(&hi));
        a0 = fmaf(wj, f0.x, a0);
        a1 = fmaf(wj, f0.y, a1);
        a2 = fmaf(wj, f1.x, a2);
        a3 = fmaf(wj, f1.y, a3);
    }

    {
        float t, u;
        t = __shfl_down_sync(0xffffffffu, a0, 9);
        u = __shfl_down_sync(0xffffffffu, a0, 18);
        a0 += t + u;
        t = __shfl_down_sync(0xffffffffu, a1, 9);
        u = __shfl_down_sync(0xffffffffu, a1, 18);
        a1 += t + u;
        t = __shfl_down_sync(0xffffffffu, a2, 9);
        u = __shfl_down_sync(0xffffffffu, a2, 18);
        a2 += t + u;
        t = __shfl_down_sync(0xffffffffu, a3, 9);
        u = __shfl_down_sync(0xffffffffu, a3, 18);
        a3 += t + u;
    }

    if (lane < 9) {
        float inv = 1.0f / wsum;
        float4 o = make_float4(a0 * inv, a1 * inv, a2 * inv, a3 * inv);
        *reinterpret_cast<float4*>(m + node * MSTR + 4 * lane) = o;
    }
}

// =====================================================================
// Kernel 3 (R8 form): out = prelu([feat, m_pos, m_neg] @ W1 + b1) @ W2 + b2
// 4 threads per node; quad-cooperative x loads + width-4 shuffles;
// h exchanged via smem.
// =====================================================================
__global__ __launch_bounds__(256, 3) void update_kernel(
    const float* __restrict__ fa, const float* __restrict__ fb,
    const float* __restrict__ W1, const float* __restrict__ b1,
    const float* __restrict__ alpha_p,
    const float* __restrict__ W2, const float* __restrict__ b2,
    float* __restrict__ out)
{
    __shared__ __align__(16) float W1sh[105 * 72];   // 30240B
    __shared__ __align__(16) ull   w2p[70 * 18];     // 10080B
    __shared__ __align__(16) float hs[64 * 73];      // 18688B
    __shared__ __align__(16) ull b1p[36];
    __shared__ __align__(16) ull b2p[18];

    const int tid = threadIdx.x;
    for (int i = tid; i < 105 * 72; i += 256) {
        int k = i / 72, c = i % 72;
        W1sh[i] = (c < 70) ? W1[k * 70 + c] : 0.0f;
    }
    for (int i = tid; i < 70 * 18; i += 256) {
        int k = i / 18, j = i % 18;
        int c = 2 * j;
        w2p[i] = pack2(W2[k * EMB + c], (c + 1 < EMB) ? W2[k * EMB + c + 1] : 0.0f);
    }
    if (tid < 36) {
        int c = 2 * tid;
        b1p[tid] = pack2(b1[c], (c + 1 < 70) ? b1[c + 1] : 0.0f);
    }
    if (tid < 18) {
        int c = 2 * tid;
        b2p[tid] = pack2(b2[c], (c + 1 < EMB) ? b2[c + 1] : 0.0f);
    }
    __syncthreads();

    const int node_l = tid >> 2;
    const int role   = tid & 3;
    const int node   = blockIdx.x * 64 + node_l;           // 0 .. 2*NNODE-1
    const bool valid = (node < 2 * NNODE);
    const int  nc    = valid ? node : (2 * NNODE - 1);

    const float* xr;
    const float* m0;
    const float* m1;
    if (nc < NNODE) {
        xr = fa + nc * EMB;
        m0 = g_m[0] + nc * MSTR;
        m1 = g_m[1] + nc * MSTR;
    } else {
        int nl = nc - NNODE;
        xr = fb + nl * EMB;
        m0 = g_m[2] + nl * MSTR;
        m1 = g_m[3] + nl * MSTR;
    }
    const float alpha = __ldg(alpha_p);

    // ---- quad-cooperative x load: this role owns x[g], g = 4*i + role ----
    float xv_[27];
#pragma unroll
    for (int i = 0; i < 27; i++) {
        int g = 4 * i + role;
        float v;
        if (g < EMB)            v = xr[g];
        else if (g < 2 * EMB)   v = m0[g - EMB];
        else if (g < 3 * EMB)   v = m1[g - 2 * EMB];
        else                    v = 0.0f;
        xv_[i] = v;
    }

    // ---- GEMM1: this role computes h pairs [9*role, 9*role+9) ----
    ull acc[9];
#pragma unroll
    for (int i = 0; i < 9; i++) acc[i] = b1p[9 * role + i];

    const ull* w1base = reinterpret_cast<const ull*>(W1sh) + 9 * role;
#pragma unroll
    for (int k = 0; k < 105; k++) {
        float xv = __shfl_sync(0xffffffffu, xv_[k >> 2], k & 3, 4);
        ull xx = pack2(xv, xv);
        const ull* wr = w1base + k * 36;
#pragma unroll
        for (int i = 0; i < 9; i++) FMA2(acc[i], wr[i], xx, acc[i]);
    }

    // ---- PReLU, publish h to smem (quad lives in one warp) ----
    float* hrow = hs + node_l * 73;
#pragma unroll
    for (int i = 0; i < 9; i++) {
        float h0, h1;
        unpack2(acc[i], h0, h1);
        h0 = (h0 > 0.0f) ? h0 : alpha * h0;
        h1 = (h1 > 0.0f) ? h1 : alpha * h1;
        int c = 18 * role + 2 * i;
        hrow[c]     = h0;
        hrow[c + 1] = h1;
    }
    __syncwarp();

    // ---- GEMM2: role owns output pairs [p0, p0+np) ----
    const int p0 = (role < 2) ? role * 5 : 10 + (role - 2) * 4;
    const int np = (role < 2) ? 5 : 4;

    ull acc2[5];
#pragma unroll
    for (int q = 0; q < 5; q++) acc2[q] = (q < np) ? b2p[p0 + q] : 0ull;

#pragma unroll 2
    for (int k = 0; k < 70; k++) {
        float hv = hrow[k];
        ull xx = pack2(hv, hv);
        const ull* wr = w2p + k * 18 + p0;
#pragma unroll
        for (int q = 0; q < 5; q++)
            if (q < np) FMA2(acc2[q], wr[q], xx, acc2[q]);
    }

    if (valid) {
        float* orow = out + node * EMB;
#pragma unroll
        for (int q = 0; q < 5; q++) {
            if (q < np) {
                float v0, v1;
                unpack2(acc2[q], v0, v1);
                int c = 2 * (p0 + q);
                orow[c] = v0;
                if (c + 1 < EMB) orow[c + 1] = v1;
            }
        }
    }
}

// =====================================================================
// launch
// =====================================================================
extern "C" void kernel_launch(void* const* d_in, const int* in_sizes, int n_in,
                              void* d_out, int out_size) {
    const float* fa = (const float*)d_in[0];
    const float* fb = (const float*)d_in[1];

    TArgs t;
    const float* fsrc[4] = { fb, fb, fa, fa };
    const float* fdst[4] = { fa, fa, fb, fb };
    for (int j = 0; j < 4; j++) {
        t.fsrc[j] = fsrc[j];
        t.fdst[j] = fdst[j];
        t.W[j]   = (const float*)d_in[6 + 3 * j];
        t.b[j]   = (const float*)d_in[7 + 3 * j];
        t.att[j] = (const float*)d_in[8 + 3 * j];
    }
    AArgs a;
    a.dst[0] = (const int*)d_in[2];
    a.dst[1] = (const int*)d_in[3];
    a.dst[2] = (const int*)d_in[4];
    a.dst[3] = (const int*)d_in[5];

    const float* W1 = (const float*)d_in[18];
    const float* b1 = (const float*)d_in[19];
    const float* al = (const float*)d_in[20];
    const float* W2 = (const float*)d_in[21];
    const float* b2 = (const float*)d_in[22];
    float* out = (float*)d_out;

    dim3 tg((NNODE + 127) / 128, 4);
    transform_kernel<<<tg, 256>>>(t);

    dim3 ag((NNODE + 7) / 8, 4);
    agg_kernel<<<ag, 256>>>(a);

    dim3 ug((2 * NNODE + 63) / 64);
    update_kernel<<<ug, 256>>>(fa, fb, W1, b1, al, W2, b2, out);
}